// round 2
// baseline (speedup 1.0000x reference)
#include <cuda_runtime.h>
#include <cstdint>

// ---------------- problem constants ----------------
#define DEPTH  4
#define HEADS  8
#define DHEAD  64
#define DIM    512
#define MLPD   2048
#define RED    128
#define BB     8
#define PP     4
#define NN     256
#define TT     (BB*PP*NN)     // 8192 tokens

// ---------------- scratch (single device symbol, offsets host-side) -------
// floats:
//  X    4,194,304   residual stream
//  Y    4,194,304   LN output
//  QKV 12,582,912
//  ATT  4,194,304
//  H1  16,777,216
//  H    4,194,304
//  BX   4,194,304
//  XG   1,048,576
//  XGA    262,144
//  XL   1,048,576
//  CA   1,048,576
//  SA       8,192
static const size_t OFF_X   = 0;
static const size_t OFF_Y   = OFF_X   + (size_t)TT*DIM;
static const size_t OFF_QKV = OFF_Y   + (size_t)TT*DIM;
static const size_t OFF_ATT = OFF_QKV + (size_t)TT*3*DIM;
static const size_t OFF_H1  = OFF_ATT + (size_t)TT*DIM;
static const size_t OFF_H   = OFF_H1  + (size_t)TT*MLPD;
static const size_t OFF_BX  = OFF_H   + (size_t)TT*DIM;
static const size_t OFF_XG  = OFF_BX  + (size_t)TT*DIM;
static const size_t OFF_XGA = OFF_XG  + (size_t)BB*NN*DIM;
static const size_t OFF_XL  = OFF_XGA + (size_t)BB*NN*RED;
static const size_t OFF_CA  = OFF_XL  + (size_t)TT*RED;
static const size_t OFF_SA  = OFF_CA  + (size_t)BB*NN*DIM;
static const size_t SCRATCH_FLOATS = OFF_SA + TT;

__device__ float g_scratch[SCRATCH_FLOATS];

// ---------------- elementwise helpers ----------------
__global__ void copy_k(const float* __restrict__ a, float* __restrict__ b, int n) {
    int i = blockIdx.x * blockDim.x + threadIdx.x;
    if (i < n) b[i] = a[i];
}

// ---------------- layernorm: 1 block / token, 128 threads ----------------
__global__ __launch_bounds__(128)
void ln_k(const float* __restrict__ in, float* __restrict__ out,
          const float* __restrict__ g, const float* __restrict__ b)
{
    int t = blockIdx.x;
    int lane = threadIdx.x & 31, w = threadIdx.x >> 5;
    float4 v = ((const float4*)(in + (size_t)t*DIM))[threadIdx.x];
    float s = v.x + v.y + v.z + v.w;
    float q = v.x*v.x + v.y*v.y + v.z*v.z + v.w*v.w;
    #pragma unroll
    for (int o = 16; o; o >>= 1) {
        s += __shfl_xor_sync(0xffffffffu, s, o);
        q += __shfl_xor_sync(0xffffffffu, q, o);
    }
    __shared__ float ss[4], qq[4];
    if (lane == 0) { ss[w] = s; qq[w] = q; }
    __syncthreads();
    s = ss[0] + ss[1] + ss[2] + ss[3];
    q = qq[0] + qq[1] + qq[2] + qq[3];
    float mean = s * (1.0f / DIM);
    float var  = q * (1.0f / DIM) - mean * mean;
    float inv  = rsqrtf(var + 1e-5f);
    float4 gg = ((const float4*)g)[threadIdx.x];
    float4 bb = ((const float4*)b)[threadIdx.x];
    float4 o4;
    o4.x = (v.x - mean) * inv * gg.x + bb.x;
    o4.y = (v.y - mean) * inv * gg.y + bb.y;
    o4.z = (v.z - mean) * inv * gg.z + bb.z;
    o4.w = (v.w - mean) * inv * gg.w + bb.w;
    ((float4*)(out + (size_t)t*DIM))[threadIdx.x] = o4;
}

// ---------------- generic tiled GEMM: C[M,N] = A[M,K] @ B[K,N] + epilogue --
// BM=BN=64, BK=16, 256 threads, 4x4 per thread. All dims are multiples.
#define EPI_NONE 0
#define EPI_BIAS 1
#define EPI_GELU 2
#define EPI_SIG  3
#define EPI_RES  4

template<int EPI>
__global__ __launch_bounds__(256)
void gemm_k(const float* __restrict__ A, const float* __restrict__ B,
            float* __restrict__ C, int M, int N, int K,
            const float* __restrict__ bias, const float* __restrict__ res)
{
    __shared__ float As[16][64];
    __shared__ float Bs[16][64];
    int tx = threadIdx.x, ty = threadIdx.y;
    int tid = ty * 16 + tx;
    int m0 = blockIdx.y * 64;
    int n0 = blockIdx.x * 64;

    int a_row = tid >> 2;          // 0..63
    int a_col = (tid & 3) * 4;     // 0,4,8,12
    int b_row = tid >> 4;          // 0..15
    int b_col = (tid & 15) * 4;    // 0..60

    float acc[4][4] = {};

    for (int k0 = 0; k0 < K; k0 += 16) {
        float4 av = *(const float4*)(A + (size_t)(m0 + a_row) * K + k0 + a_col);
        As[a_col + 0][a_row] = av.x;
        As[a_col + 1][a_row] = av.y;
        As[a_col + 2][a_row] = av.z;
        As[a_col + 3][a_row] = av.w;
        *(float4*)&Bs[b_row][b_col] =
            *(const float4*)(B + (size_t)(k0 + b_row) * N + n0 + b_col);
        __syncthreads();
        #pragma unroll
        for (int k = 0; k < 16; k++) {
            float4 a = *(const float4*)&As[k][ty * 4];
            float4 b = *(const float4*)&Bs[k][tx * 4];
            float ar[4] = {a.x, a.y, a.z, a.w};
            float br[4] = {b.x, b.y, b.z, b.w};
            #pragma unroll
            for (int i = 0; i < 4; i++)
                #pragma unroll
                for (int j = 0; j < 4; j++)
                    acc[i][j] += ar[i] * br[j];
        }
        __syncthreads();
    }

    #pragma unroll
    for (int i = 0; i < 4; i++) {
        int m = m0 + ty * 4 + i;
        #pragma unroll
        for (int j = 0; j < 4; j++) {
            int n = n0 + tx * 4 + j;
            float v = acc[i][j];
            if (EPI != EPI_NONE) v += bias[n];
            if (EPI == EPI_GELU)      v = 0.5f * v * (1.0f + erff(v * 0.70710678118654752f));
            else if (EPI == EPI_SIG)  v = 1.0f / (1.0f + __expf(-v));
            else if (EPI == EPI_RES)  v += res[(size_t)m * N + n];
            C[(size_t)m * N + n] = v;
        }
    }
}

// ---------------- attention: 1 block per (b,p,h), 256 threads -------------
// K,V tiles resident in 128KB dynamic smem; one query per thread; two-pass softmax.
__global__ __launch_bounds__(256)
void attn_k(const float* __restrict__ qkv, float* __restrict__ out)
{
    extern __shared__ float sm[];
    float* Ks = sm;                 // 256*64
    float* Vs = sm + NN * DHEAD;    // 256*64
    int bid = blockIdx.x;
    int h  = bid & 7;
    int bp = bid >> 3;              // b*4+p
    int tbase = bp * NN;
    int hoff = h * DHEAD;

    for (int idx = threadIdx.x; idx < NN * DHEAD; idx += 256) {
        int r = idx >> 6, c = idx & 63;
        size_t g = (size_t)(tbase + r) * (3 * DIM);
        Ks[idx] = qkv[g + DIM     + hoff + c];
        Vs[idx] = qkv[g + 2 * DIM + hoff + c];
    }
    __syncthreads();

    int t = tbase + threadIdx.x;
    float q[64];
    {
        const float4* qp = (const float4*)(qkv + (size_t)t * (3 * DIM) + hoff);
        #pragma unroll
        for (int i = 0; i < 16; i++) {
            float4 v = qp[i];
            q[4*i] = v.x; q[4*i+1] = v.y; q[4*i+2] = v.z; q[4*i+3] = v.w;
        }
    }
    const float scale = 0.125f;   // DHEAD^-0.5

    // pass 1: row max
    float m = -1e30f;
    for (int j = 0; j < NN; j++) {
        const float4* kp = (const float4*)(Ks + j * 64);
        float s = 0.f;
        #pragma unroll
        for (int i = 0; i < 16; i++) {
            float4 kv = kp[i];
            s += q[4*i]*kv.x + q[4*i+1]*kv.y + q[4*i+2]*kv.z + q[4*i+3]*kv.w;
        }
        m = fmaxf(m, s * scale);
    }

    // pass 2: exp-weighted accumulate
    float o[64];
    #pragma unroll
    for (int i = 0; i < 64; i++) o[i] = 0.f;
    float l = 0.f;
    for (int j = 0; j < NN; j++) {
        const float4* kp = (const float4*)(Ks + j * 64);
        float s = 0.f;
        #pragma unroll
        for (int i = 0; i < 16; i++) {
            float4 kv = kp[i];
            s += q[4*i]*kv.x + q[4*i+1]*kv.y + q[4*i+2]*kv.z + q[4*i+3]*kv.w;
        }
        float p = __expf(s * scale - m);
        l += p;
        const float4* vp = (const float4*)(Vs + j * 64);
        #pragma unroll
        for (int i = 0; i < 16; i++) {
            float4 vv = vp[i];
            o[4*i]   += p * vv.x;
            o[4*i+1] += p * vv.y;
            o[4*i+2] += p * vv.z;
            o[4*i+3] += p * vv.w;
        }
    }
    float inv = 1.0f / l;
    float* op = out + (size_t)t * DIM + hoff;
    #pragma unroll
    for (int i = 0; i < 16; i++) {
        float4 v;
        v.x = o[4*i]   * inv;
        v.y = o[4*i+1] * inv;
        v.z = o[4*i+2] * inv;
        v.w = o[4*i+3] * inv;
        ((float4*)op)[i] = v;
    }
}

// ---------------- biattn pieces ----------------
// x_global[b,n,:] = mean over p of bx
__global__ void mean_k(const float* __restrict__ bx, float* __restrict__ xg)
{
    int idx = blockIdx.x * blockDim.x + threadIdx.x;
    if (idx >= BB * NN * DIM) return;
    int d = idx % DIM;
    int n = (idx / DIM) % NN;
    int b = idx / (DIM * NN);
    size_t base = ((size_t)(b * PP) * NN + n) * DIM + d;
    const size_t st = (size_t)NN * DIM;
    xg[idx] = 0.25f * (bx[base] + bx[base + st] + bx[base + 2*st] + bx[base + 3*st]);
}

// s_attn: one warp per token: sigmoid(dot([xl_t, xga_{b,n}], ws) + bs)
__global__ __launch_bounds__(256)
void sattn_k(const float* __restrict__ xl, const float* __restrict__ xga,
             const float* __restrict__ ws, const float* __restrict__ bsc,
             float* __restrict__ sa)
{
    int gtid = blockIdx.x * 256 + threadIdx.x;
    int t = gtid >> 5;
    int lane = threadIdx.x & 31;
    if (t >= TT) return;
    int b = t / (PP * NN);
    int n = t % NN;
    const float* xlp = xl  + (size_t)t * RED;
    const float* xgp = xga + ((size_t)b * NN + n) * RED;
    float s = 0.f;
    for (int i = lane; i < RED; i += 32)
        s += xlp[i] * ws[i] + xgp[i] * ws[RED + i];
    #pragma unroll
    for (int o = 16; o; o >>= 1) s += __shfl_xor_sync(0xffffffffu, s, o);
    if (lane == 0) sa[t] = 1.0f / (1.0f + __expf(-(s + bsc[0])));
}

// x += h * c_attn[b,n,:] * s_attn[t]
__global__ void fuse_k(const float* __restrict__ h, const float* __restrict__ ca,
                       const float* __restrict__ sa, float* __restrict__ x)
{
    int idx = blockIdx.x * blockDim.x + threadIdx.x;
    if (idx >= TT * DIM) return;
    int t = idx / DIM;
    int d = idx % DIM;
    int b = t / (PP * NN);
    int n = t % NN;
    x[idx] += h[idx] * ca[((size_t)b * NN + n) * DIM + d] * sa[t];
}

// ---------------- host driver ----------------
extern "C" void kernel_launch(void* const* d_in, const int* in_sizes, int n_in,
                              void* d_out, int out_size)
{
    const float* x_in  = (const float*)d_in[0];
    const float* ln1_g = (const float*)d_in[1];
    const float* ln1_b = (const float*)d_in[2];
    const float* w_qkv = (const float*)d_in[3];
    const float* w_o   = (const float*)d_in[4];
    const float* b_o   = (const float*)d_in[5];
    const float* ln2_g = (const float*)d_in[6];
    const float* ln2_b = (const float*)d_in[7];
    const float* w1    = (const float*)d_in[8];
    const float* b1    = (const float*)d_in[9];
    const float* w2    = (const float*)d_in[10];
    const float* b2    = (const float*)d_in[11];
    const float* bn_g  = (const float*)d_in[12];
    const float* bn_b  = (const float*)d_in[13];
    const float* wg    = (const float*)d_in[14];
    const float* bg    = (const float*)d_in[15];
    const float* wl    = (const float*)d_in[16];
    const float* bl    = (const float*)d_in[17];
    const float* wc    = (const float*)d_in[18];
    const float* bc    = (const float*)d_in[19];
    const float* ws    = (const float*)d_in[20];
    const float* bs    = (const float*)d_in[21];

    float* base = nullptr;
    cudaGetSymbolAddress((void**)&base, g_scratch);
    float* X   = base + OFF_X;
    float* Y   = base + OFF_Y;
    float* QKV = base + OFF_QKV;
    float* ATT = base + OFF_ATT;
    float* H1  = base + OFF_H1;
    float* H   = base + OFF_H;
    float* BX  = base + OFF_BX;
    float* XG  = base + OFF_XG;
    float* XGA = base + OFF_XGA;
    float* XL  = base + OFF_XL;
    float* CA  = base + OFF_CA;
    float* SA  = base + OFF_SA;

    const int ATTN_SMEM = 2 * NN * DHEAD * sizeof(float);   // 128 KB
    cudaFuncSetAttribute((const void*)attn_k,
                         cudaFuncAttributeMaxDynamicSharedMemorySize, ATTN_SMEM);

    dim3 tb(16, 16);
    const int EW = 256;

    copy_k<<<(TT*DIM + EW - 1) / EW, EW>>>(x_in, X, TT * DIM);

    for (int l = 0; l < DEPTH; l++) {
        // ---- attention half ----
        ln_k<<<TT, 128>>>(X, Y, ln1_g + l*DIM, ln1_b + l*DIM);
        gemm_k<EPI_NONE><<<dim3(3*DIM/64, TT/64), tb>>>(
            Y, w_qkv + (size_t)l*DIM*3*DIM, QKV, TT, 3*DIM, DIM, nullptr, nullptr);
        attn_k<<<BB*PP*HEADS, 256, ATTN_SMEM>>>(QKV, ATT);
        gemm_k<EPI_RES><<<dim3(DIM/64, TT/64), tb>>>(
            ATT, w_o + (size_t)l*DIM*DIM, X, TT, DIM, DIM, b_o + l*DIM, X);

        // ---- mlp half ----
        ln_k<<<TT, 128>>>(X, Y, ln2_g + l*DIM, ln2_b + l*DIM);
        gemm_k<EPI_GELU><<<dim3(MLPD/64, TT/64), tb>>>(
            Y, w1 + (size_t)l*DIM*MLPD, H1, TT, MLPD, DIM, b1 + l*MLPD, nullptr);
        gemm_k<EPI_BIAS><<<dim3(DIM/64, TT/64), tb>>>(
            H1, w2 + (size_t)l*MLPD*DIM, H, TT, DIM, MLPD, b2 + l*DIM, nullptr);

        // ---- biattn ----
        ln_k<<<TT, 128>>>(H, BX, bn_g + l*DIM, bn_b + l*DIM);
        mean_k<<<(BB*NN*DIM + EW - 1) / EW, EW>>>(BX, XG);
        gemm_k<EPI_GELU><<<dim3(RED/64, BB*NN/64), tb>>>(
            XG, wg + (size_t)l*DIM*RED, XGA, BB*NN, RED, DIM, bg + l*RED, nullptr);
        gemm_k<EPI_GELU><<<dim3(RED/64, TT/64), tb>>>(
            BX, wl + (size_t)l*DIM*RED, XL, TT, RED, DIM, bl + l*RED, nullptr);
        gemm_k<EPI_SIG><<<dim3(DIM/64, BB*NN/64), tb>>>(
            XGA, wc + (size_t)l*RED*DIM, CA, BB*NN, DIM, RED, bc + l*DIM, nullptr);
        sattn_k<<<(TT*32 + 255) / 256, 256>>>(XL, XGA, ws + l*2*RED, bs + l, SA);
        fuse_k<<<(TT*DIM + EW - 1) / EW, EW>>>(H, CA, SA, X);
    }

    copy_k<<<(TT*DIM + EW - 1) / EW, EW>>>(X, (float*)d_out, TT * DIM);
}

// round 6
// speedup vs baseline: 2.1816x; 2.1816x over previous
#include <cuda_runtime.h>
#include <cstdint>

// ---------------- problem constants ----------------
#define DEPTH  4
#define HEADS  8
#define DHEAD  64
#define DIM    512
#define MLPD   2048
#define RED    128
#define BB     8
#define PP     4
#define NN     256
#define TT     (BB*PP*NN)     // 8192 tokens

// ---------------- scratch ----------------
static const size_t OFF_X   = 0;
static const size_t OFF_Y   = OFF_X   + (size_t)TT*DIM;
static const size_t OFF_QKV = OFF_Y   + (size_t)TT*DIM;
static const size_t OFF_ATT = OFF_QKV + (size_t)TT*3*DIM;
static const size_t OFF_H1  = OFF_ATT + (size_t)TT*DIM;
static const size_t OFF_H   = OFF_H1  + (size_t)TT*MLPD;
static const size_t OFF_BX  = OFF_H   + (size_t)TT*DIM;
static const size_t OFF_XG  = OFF_BX  + (size_t)TT*DIM;
static const size_t OFF_XGA = OFF_XG  + (size_t)BB*NN*DIM;
static const size_t OFF_XL  = OFF_XGA + (size_t)BB*NN*RED;
static const size_t OFF_CA  = OFF_XL  + (size_t)TT*RED;
static const size_t OFF_SA  = OFF_CA  + (size_t)BB*NN*DIM;
static const size_t SCRATCH_FLOATS = OFF_SA + TT;

__device__ float g_scratch[SCRATCH_FLOATS];

// ---------------- helpers ----------------
__global__ void copy_k(const float* __restrict__ a, float* __restrict__ b, int n) {
    int i = blockIdx.x * blockDim.x + threadIdx.x;
    if (i < n) b[i] = a[i];
}

__device__ __forceinline__ uint32_t f2tf32(float v) {
    uint32_t r;
    asm("cvt.rna.tf32.f32 %0, %1;" : "=r"(r) : "f"(v));
    return r;
}

// ---------------- layernorm ----------------
__global__ __launch_bounds__(128)
void ln_k(const float* __restrict__ in, float* __restrict__ out,
          const float* __restrict__ g, const float* __restrict__ b)
{
    int t = blockIdx.x;
    int lane = threadIdx.x & 31, w = threadIdx.x >> 5;
    float4 v = ((const float4*)(in + (size_t)t*DIM))[threadIdx.x];
    float s = v.x + v.y + v.z + v.w;
    float q = v.x*v.x + v.y*v.y + v.z*v.z + v.w*v.w;
    #pragma unroll
    for (int o = 16; o; o >>= 1) {
        s += __shfl_xor_sync(0xffffffffu, s, o);
        q += __shfl_xor_sync(0xffffffffu, q, o);
    }
    __shared__ float ss[4], qq[4];
    if (lane == 0) { ss[w] = s; qq[w] = q; }
    __syncthreads();
    s = ss[0] + ss[1] + ss[2] + ss[3];
    q = qq[0] + qq[1] + qq[2] + qq[3];
    float mean = s * (1.0f / DIM);
    float var  = q * (1.0f / DIM) - mean * mean;
    float inv  = rsqrtf(var + 1e-5f);
    float4 gg = ((const float4*)g)[threadIdx.x];
    float4 bb = ((const float4*)b)[threadIdx.x];
    float4 o4;
    o4.x = (v.x - mean) * inv * gg.x + bb.x;
    o4.y = (v.y - mean) * inv * gg.y + bb.y;
    o4.z = (v.z - mean) * inv * gg.z + bb.z;
    o4.w = (v.w - mean) * inv * gg.w + bb.w;
    ((float4*)(out + (size_t)t*DIM))[threadIdx.x] = o4;
}

// ---------------- tf32 tensor-core GEMM -----------------------------------
// C[M,N] = A[M,K] @ B[K,N] (+ epilogue). BM=BN=128, BK=16, 256 threads,
// 8 warps in 2x4, warp tile 64x32 built from m16n8k8 tf32 mma.
// Requires: M%128==0, N%128==0, K%16==0 (all shapes here satisfy this).
#define EPI_NONE 0
#define EPI_BIAS 1
#define EPI_GELU 2
#define EPI_SIG  3
#define EPI_RES  4

#define SSTR 136   // smem row stride (floats): banks = tig*8+group, conflict-free

template<int EPI>
__global__ __launch_bounds__(256)
void tgemm_k(const float* __restrict__ A, const float* __restrict__ B,
             float* __restrict__ C, int M, int N, int K,
             const float* __restrict__ bias, const float* __restrict__ res)
{
    __shared__ uint32_t As[2][16][SSTR];
    __shared__ uint32_t Bs[2][16][SSTR];

    const int tid   = threadIdx.x;
    const int warp  = tid >> 5, lane = tid & 31;
    const int group = lane >> 2, tig = lane & 3;
    const int wm = (warp >> 2) * 64;
    const int wn = (warp & 3) * 32;
    const int m0 = blockIdx.y * 128, n0 = blockIdx.x * 128;

    const int ar = tid >> 2;          // 0..63 (A row within half-tile)
    const int ac = (tid & 3) * 4;     // 0,4,8,12 (A k-col)
    const int br = tid >> 5;          // 0..7   (B k-row within half-tile)
    const int bc = (tid & 31) * 4;    // 0..124 (B n-col)

    float4 rA[2], rB[2];

    // prologue: stage tile 0
    #pragma unroll
    for (int i = 0; i < 2; i++) {
        rA[i] = *(const float4*)(A + (size_t)(m0 + ar + i*64) * K + ac);
        rB[i] = *(const float4*)(B + (size_t)(br + i*8) * N + n0 + bc);
    }
    #pragma unroll
    for (int i = 0; i < 2; i++) {
        As[0][ac+0][ar+i*64] = f2tf32(rA[i].x);
        As[0][ac+1][ar+i*64] = f2tf32(rA[i].y);
        As[0][ac+2][ar+i*64] = f2tf32(rA[i].z);
        As[0][ac+3][ar+i*64] = f2tf32(rA[i].w);
        Bs[0][br+i*8][bc+0]  = f2tf32(rB[i].x);
        Bs[0][br+i*8][bc+1]  = f2tf32(rB[i].y);
        Bs[0][br+i*8][bc+2]  = f2tf32(rB[i].z);
        Bs[0][br+i*8][bc+3]  = f2tf32(rB[i].w);
    }
    __syncthreads();

    float c[4][4][4];
    #pragma unroll
    for (int mi = 0; mi < 4; mi++)
        #pragma unroll
        for (int ni = 0; ni < 4; ni++)
            #pragma unroll
            for (int r = 0; r < 4; r++) c[mi][ni][r] = 0.f;

    const int nk = K / 16;
    for (int kt = 0; kt < nk; kt++) {
        const int buf = kt & 1;
        const bool pf = (kt + 1 < nk);
        if (pf) {
            int k0 = (kt + 1) * 16;
            #pragma unroll
            for (int i = 0; i < 2; i++) {
                rA[i] = *(const float4*)(A + (size_t)(m0 + ar + i*64) * K + k0 + ac);
                rB[i] = *(const float4*)(B + (size_t)(k0 + br + i*8) * N + n0 + bc);
            }
        }

        #pragma unroll
        for (int k8 = 0; k8 < 2; k8++) {
            uint32_t a[4][4], b[4][2];
            const int kr0 = k8*8 + tig, kr1 = k8*8 + tig + 4;
            #pragma unroll
            for (int mi = 0; mi < 4; mi++) {
                int mm = wm + mi*16 + group;
                a[mi][0] = As[buf][kr0][mm];
                a[mi][1] = As[buf][kr0][mm+8];
                a[mi][2] = As[buf][kr1][mm];
                a[mi][3] = As[buf][kr1][mm+8];
            }
            #pragma unroll
            for (int ni = 0; ni < 4; ni++) {
                int nn = wn + ni*8 + group;
                b[ni][0] = Bs[buf][kr0][nn];
                b[ni][1] = Bs[buf][kr1][nn];
            }
            #pragma unroll
            for (int mi = 0; mi < 4; mi++)
                #pragma unroll
                for (int ni = 0; ni < 4; ni++) {
                    asm volatile(
                        "mma.sync.aligned.m16n8k8.row.col.f32.tf32.tf32.f32 "
                        "{%0,%1,%2,%3}, {%4,%5,%6,%7}, {%8,%9}, {%0,%1,%2,%3};"
                        : "+f"(c[mi][ni][0]), "+f"(c[mi][ni][1]),
                          "+f"(c[mi][ni][2]), "+f"(c[mi][ni][3])
                        : "r"(a[mi][0]), "r"(a[mi][1]), "r"(a[mi][2]), "r"(a[mi][3]),
                          "r"(b[ni][0]), "r"(b[ni][1]));
                }
        }

        if (pf) {
            const int nb = buf ^ 1;
            #pragma unroll
            for (int i = 0; i < 2; i++) {
                As[nb][ac+0][ar+i*64] = f2tf32(rA[i].x);
                As[nb][ac+1][ar+i*64] = f2tf32(rA[i].y);
                As[nb][ac+2][ar+i*64] = f2tf32(rA[i].z);
                As[nb][ac+3][ar+i*64] = f2tf32(rA[i].w);
                Bs[nb][br+i*8][bc+0]  = f2tf32(rB[i].x);
                Bs[nb][br+i*8][bc+1]  = f2tf32(rB[i].y);
                Bs[nb][br+i*8][bc+2]  = f2tf32(rB[i].z);
                Bs[nb][br+i*8][bc+3]  = f2tf32(rB[i].w);
            }
        }
        __syncthreads();
    }

    // epilogue
    #pragma unroll
    for (int mi = 0; mi < 4; mi++) {
        #pragma unroll
        for (int half = 0; half < 2; half++) {
            int m = m0 + wm + mi*16 + group + half*8;
            #pragma unroll
            for (int ni = 0; ni < 4; ni++) {
                int n = n0 + wn + ni*8 + tig*2;
                float v0 = c[mi][ni][half*2 + 0];
                float v1 = c[mi][ni][half*2 + 1];
                if (EPI != EPI_NONE) { v0 += bias[n]; v1 += bias[n+1]; }
                if (EPI == EPI_GELU) {
                    v0 = 0.5f * v0 * (1.0f + erff(v0 * 0.70710678118654752f));
                    v1 = 0.5f * v1 * (1.0f + erff(v1 * 0.70710678118654752f));
                } else if (EPI == EPI_SIG) {
                    v0 = 1.0f / (1.0f + __expf(-v0));
                    v1 = 1.0f / (1.0f + __expf(-v1));
                } else if (EPI == EPI_RES) {
                    v0 += res[(size_t)m * N + n];
                    v1 += res[(size_t)m * N + n + 1];
                }
                float2 o = make_float2(v0, v1);
                *(float2*)(C + (size_t)m * N + n) = o;
            }
        }
    }
}

// ---------------- attention: 1 block per (b,p,h), 256 threads -------------
__global__ __launch_bounds__(256)
void attn_k(const float* __restrict__ qkv, float* __restrict__ out)
{
    extern __shared__ float sm[];
    float* Ks = sm;
    float* Vs = sm + NN * DHEAD;
    int bid = blockIdx.x;
    int h  = bid & 7;
    int bp = bid >> 3;
    int tbase = bp * NN;
    int hoff = h * DHEAD;

    for (int idx = threadIdx.x; idx < NN * DHEAD; idx += 256) {
        int r = idx >> 6, c = idx & 63;
        size_t g = (size_t)(tbase + r) * (3 * DIM);
        Ks[idx] = qkv[g + DIM     + hoff + c];
        Vs[idx] = qkv[g + 2 * DIM + hoff + c];
    }
    __syncthreads();

    int t = tbase + threadIdx.x;
    float q[64];
    {
        const float4* qp = (const float4*)(qkv + (size_t)t * (3 * DIM) + hoff);
        #pragma unroll
        for (int i = 0; i < 16; i++) {
            float4 v = qp[i];
            q[4*i] = v.x; q[4*i+1] = v.y; q[4*i+2] = v.z; q[4*i+3] = v.w;
        }
    }
    const float scale = 0.125f;

    float m = -1e30f;
    for (int j = 0; j < NN; j++) {
        const float4* kp = (const float4*)(Ks + j * 64);
        float s = 0.f;
        #pragma unroll
        for (int i = 0; i < 16; i++) {
            float4 kv = kp[i];
            s += q[4*i]*kv.x + q[4*i+1]*kv.y + q[4*i+2]*kv.z + q[4*i+3]*kv.w;
        }
        m = fmaxf(m, s * scale);
    }

    float o[64];
    #pragma unroll
    for (int i = 0; i < 64; i++) o[i] = 0.f;
    float l = 0.f;
    for (int j = 0; j < NN; j++) {
        const float4* kp = (const float4*)(Ks + j * 64);
        float s = 0.f;
        #pragma unroll
        for (int i = 0; i < 16; i++) {
            float4 kv = kp[i];
            s += q[4*i]*kv.x + q[4*i+1]*kv.y + q[4*i+2]*kv.z + q[4*i+3]*kv.w;
        }
        float p = __expf(s * scale - m);
        l += p;
        const float4* vp = (const float4*)(Vs + j * 64);
        #pragma unroll
        for (int i = 0; i < 16; i++) {
            float4 vv = vp[i];
            o[4*i]   += p * vv.x;
            o[4*i+1] += p * vv.y;
            o[4*i+2] += p * vv.z;
            o[4*i+3] += p * vv.w;
        }
    }
    float inv = 1.0f / l;
    float* op = out + (size_t)t * DIM + hoff;
    #pragma unroll
    for (int i = 0; i < 16; i++) {
        float4 v;
        v.x = o[4*i]   * inv;
        v.y = o[4*i+1] * inv;
        v.z = o[4*i+2] * inv;
        v.w = o[4*i+3] * inv;
        ((float4*)op)[i] = v;
    }
}

// ---------------- biattn pieces ----------------
__global__ void mean_k(const float* __restrict__ bx, float* __restrict__ xg)
{
    int idx = blockIdx.x * blockDim.x + threadIdx.x;
    if (idx >= BB * NN * DIM) return;
    int d = idx % DIM;
    int n = (idx / DIM) % NN;
    int b = idx / (DIM * NN);
    size_t base = ((size_t)(b * PP) * NN + n) * DIM + d;
    const size_t st = (size_t)NN * DIM;
    xg[idx] = 0.25f * (bx[base] + bx[base + st] + bx[base + 2*st] + bx[base + 3*st]);
}

__global__ __launch_bounds__(256)
void sattn_k(const float* __restrict__ xl, const float* __restrict__ xga,
             const float* __restrict__ ws, const float* __restrict__ bsc,
             float* __restrict__ sa)
{
    int gtid = blockIdx.x * 256 + threadIdx.x;
    int t = gtid >> 5;
    int lane = threadIdx.x & 31;
    if (t >= TT) return;
    int b = t / (PP * NN);
    int n = t % NN;
    const float* xlp = xl  + (size_t)t * RED;
    const float* xgp = xga + ((size_t)b * NN + n) * RED;
    float s = 0.f;
    for (int i = lane; i < RED; i += 32)
        s += xlp[i] * ws[i] + xgp[i] * ws[RED + i];
    #pragma unroll
    for (int o = 16; o; o >>= 1) s += __shfl_xor_sync(0xffffffffu, s, o);
    if (lane == 0) sa[t] = 1.0f / (1.0f + __expf(-(s + bsc[0])));
}

__global__ void fuse_k(const float* __restrict__ h, const float* __restrict__ ca,
                       const float* __restrict__ sa, float* __restrict__ x)
{
    int idx = blockIdx.x * blockDim.x + threadIdx.x;
    if (idx >= TT * DIM) return;
    int t = idx / DIM;
    int d = idx % DIM;
    int b = t / (PP * NN);
    int n = t % NN;
    x[idx] += h[idx] * ca[((size_t)b * NN + n) * DIM + d] * sa[t];
}

// ---------------- host driver ----------------
extern "C" void kernel_launch(void* const* d_in, const int* in_sizes, int n_in,
                              void* d_out, int out_size)
{
    const float* x_in  = (const float*)d_in[0];
    const float* ln1_g = (const float*)d_in[1];
    const float* ln1_b = (const float*)d_in[2];
    const float* w_qkv = (const float*)d_in[3];
    const float* w_o   = (const float*)d_in[4];
    const float* b_o   = (const float*)d_in[5];
    const float* ln2_g = (const float*)d_in[6];
    const float* ln2_b = (const float*)d_in[7];
    const float* w1    = (const float*)d_in[8];
    const float* b1    = (const float*)d_in[9];
    const float* w2    = (const float*)d_in[10];
    const float* b2    = (const float*)d_in[11];
    const float* bn_g  = (const float*)d_in[12];
    const float* bn_b  = (const float*)d_in[13];
    const float* wg    = (const float*)d_in[14];
    const float* bg    = (const float*)d_in[15];
    const float* wl    = (const float*)d_in[16];
    const float* bl    = (const float*)d_in[17];
    const float* wc    = (const float*)d_in[18];
    const float* bc    = (const float*)d_in[19];
    const float* ws    = (const float*)d_in[20];
    const float* bs    = (const float*)d_in[21];

    float* base = nullptr;
    cudaGetSymbolAddress((void**)&base, g_scratch);
    float* X   = base + OFF_X;
    float* Y   = base + OFF_Y;
    float* QKV = base + OFF_QKV;
    float* ATT = base + OFF_ATT;
    float* H1  = base + OFF_H1;
    float* H   = base + OFF_H;
    float* BX  = base + OFF_BX;
    float* XG  = base + OFF_XG;
    float* XGA = base + OFF_XGA;
    float* XL  = base + OFF_XL;
    float* CA  = base + OFF_CA;
    float* SA  = base + OFF_SA;

    const int ATTN_SMEM = 2 * NN * DHEAD * sizeof(float);   // 128 KB
    cudaFuncSetAttribute((const void*)attn_k,
                         cudaFuncAttributeMaxDynamicSharedMemorySize, ATTN_SMEM);

    const int EW = 256;

    copy_k<<<(TT*DIM + EW - 1) / EW, EW>>>(x_in, X, TT * DIM);

    for (int l = 0; l < DEPTH; l++) {
        // ---- attention half ----
        ln_k<<<TT, 128>>>(X, Y, ln1_g + l*DIM, ln1_b + l*DIM);
        tgemm_k<EPI_NONE><<<dim3(3*DIM/128, TT/128), 256>>>(
            Y, w_qkv + (size_t)l*DIM*3*DIM, QKV, TT, 3*DIM, DIM, nullptr, nullptr);
        attn_k<<<BB*PP*HEADS, 256, ATTN_SMEM>>>(QKV, ATT);
        tgemm_k<EPI_RES><<<dim3(DIM/128, TT/128), 256>>>(
            ATT, w_o + (size_t)l*DIM*DIM, X, TT, DIM, DIM, b_o + l*DIM, X);

        // ---- mlp half ----
        ln_k<<<TT, 128>>>(X, Y, ln2_g + l*DIM, ln2_b + l*DIM);
        tgemm_k<EPI_GELU><<<dim3(MLPD/128, TT/128), 256>>>(
            Y, w1 + (size_t)l*DIM*MLPD, H1, TT, MLPD, DIM, b1 + l*MLPD, nullptr);
        tgemm_k<EPI_BIAS><<<dim3(DIM/128, TT/128), 256>>>(
            H1, w2 + (size_t)l*MLPD*DIM, H, TT, DIM, MLPD, b2 + l*DIM, nullptr);

        // ---- biattn ----
        ln_k<<<TT, 128>>>(H, BX, bn_g + l*DIM, bn_b + l*DIM);
        mean_k<<<(BB*NN*DIM + EW - 1) / EW, EW>>>(BX, XG);
        tgemm_k<EPI_GELU><<<dim3(RED/128, BB*NN/128), 256>>>(
            XG, wg + (size_t)l*DIM*RED, XGA, BB*NN, RED, DIM, bg + l*RED, nullptr);
        tgemm_k<EPI_GELU><<<dim3(RED/128, TT/128), 256>>>(
            BX, wl + (size_t)l*DIM*RED, XL, TT, RED, DIM, bl + l*RED, nullptr);
        tgemm_k<EPI_SIG><<<dim3(DIM/128, BB*NN/128), 256>>>(
            XGA, wc + (size_t)l*RED*DIM, CA, BB*NN, DIM, RED, bc + l*DIM, nullptr);
        sattn_k<<<(TT*32 + 255) / 256, 256>>>(XL, XGA, ws + l*2*RED, bs + l, SA);
        fuse_k<<<(TT*DIM + EW - 1) / EW, EW>>>(H, CA, SA, X);
    }

    copy_k<<<(TT*DIM + EW - 1) / EW, EW>>>(X, (float*)d_out, TT * DIM);
}

// round 7
// speedup vs baseline: 3.1382x; 1.4385x over previous
#include <cuda_runtime.h>
#include <cuda_bf16.h>
#include <cstdint>

// ---------------- problem constants ----------------
#define DEPTH  4
#define HEADS  8
#define DHEAD  64
#define DIM    512
#define MLPD   2048
#define RED    128
#define BB     8
#define PP     4
#define NN     256
#define TT     (BB*PP*NN)     // 8192 tokens

// ---------------- scratch ----------------
static const size_t OFF_X   = 0;                               // f32 residual
static const size_t OFF_Y   = OFF_X   + (size_t)TT*DIM;        // bf16 LN out
static const size_t OFF_QKV = OFF_Y   + (size_t)TT*DIM;        // f32
static const size_t OFF_ATT = OFF_QKV + (size_t)TT*3*DIM;      // bf16
static const size_t OFF_H1  = OFF_ATT + (size_t)TT*DIM;        // bf16
static const size_t OFF_H   = OFF_H1  + (size_t)TT*MLPD;       // f32
static const size_t OFF_BX  = OFF_H   + (size_t)TT*DIM;        // bf16
static const size_t OFF_XG  = OFF_BX  + (size_t)TT*DIM;        // bf16
static const size_t OFF_XGA = OFF_XG  + (size_t)BB*NN*DIM;     // bf16
static const size_t OFF_XL  = OFF_XGA + (size_t)BB*NN*RED;     // bf16
static const size_t OFF_CA  = OFF_XL  + (size_t)TT*RED;        // f32
static const size_t OFF_SA  = OFF_CA  + (size_t)BB*NN*DIM;     // f32
static const size_t OFF_WP  = OFF_SA  + TT;                    // packed bf16x2 weights (uint32)

// packed-weight sub-offsets (uint32 units)
static const size_t WP_QKV = 0;                                   // 4*256*1536
static const size_t WP_O   = WP_QKV + (size_t)4*256*1536;         // 4*256*512
static const size_t WP_W1  = WP_O   + (size_t)4*256*512;          // 4*256*2048
static const size_t WP_W2  = WP_W1  + (size_t)4*256*2048;         // 4*1024*512
static const size_t WP_WG  = WP_W2  + (size_t)4*1024*512;         // 4*256*128
static const size_t WP_WL  = WP_WG  + (size_t)4*256*128;          // 4*256*128
static const size_t WP_WC  = WP_WL  + (size_t)4*256*128;          // 4*64*512
static const size_t WP_TOT = WP_WC  + (size_t)4*64*512;

static const size_t SCRATCH_FLOATS = OFF_WP + WP_TOT;

__device__ float g_scratch[SCRATCH_FLOATS];

// ---------------- helpers ----------------
__global__ void copy_k(const float* __restrict__ a, float* __restrict__ b, int n) {
    int i = blockIdx.x * blockDim.x + threadIdx.x;
    if (i < n) b[i] = a[i];
}

// pack fp32 weights [D][K][N] -> bf16x2 pairs along K: Wp[(d*(K/2)+p)*N + n]
__global__ void packw_k(const float* __restrict__ W, uint32_t* __restrict__ Wp,
                        int K, int N, int total)
{
    int idx = blockIdx.x * blockDim.x + threadIdx.x;
    if (idx >= total) return;
    int n  = idx % N;
    int rp = idx / N;
    int p  = rp % (K >> 1);
    int d  = rp / (K >> 1);
    const float* s = W + ((size_t)d * K + 2 * p) * N + n;
    __nv_bfloat162 h = __floats2bfloat162_rn(s[0], s[N]);
    ((__nv_bfloat162*)Wp)[idx] = h;
}

// ---------------- layernorm: fp32 in, bf16 out ----------------
__global__ __launch_bounds__(128)
void ln_k(const float* __restrict__ in, __nv_bfloat16* __restrict__ out,
          const float* __restrict__ g, const float* __restrict__ b)
{
    int t = blockIdx.x;
    int lane = threadIdx.x & 31, w = threadIdx.x >> 5;
    float4 v = ((const float4*)(in + (size_t)t*DIM))[threadIdx.x];
    float s = v.x + v.y + v.z + v.w;
    float q = v.x*v.x + v.y*v.y + v.z*v.z + v.w*v.w;
    #pragma unroll
    for (int o = 16; o; o >>= 1) {
        s += __shfl_xor_sync(0xffffffffu, s, o);
        q += __shfl_xor_sync(0xffffffffu, q, o);
    }
    __shared__ float ss[4], qq[4];
    if (lane == 0) { ss[w] = s; qq[w] = q; }
    __syncthreads();
    s = ss[0] + ss[1] + ss[2] + ss[3];
    q = qq[0] + qq[1] + qq[2] + qq[3];
    float mean = s * (1.0f / DIM);
    float var  = q * (1.0f / DIM) - mean * mean;
    float inv  = rsqrtf(var + 1e-5f);
    float4 gg = ((const float4*)g)[threadIdx.x];
    float4 bb = ((const float4*)b)[threadIdx.x];
    float o0 = (v.x - mean) * inv * gg.x + bb.x;
    float o1 = (v.y - mean) * inv * gg.y + bb.y;
    float o2 = (v.z - mean) * inv * gg.z + bb.z;
    float o3 = (v.w - mean) * inv * gg.w + bb.w;
    __nv_bfloat162* op = (__nv_bfloat162*)(out + (size_t)t*DIM) + 2*threadIdx.x;
    op[0] = __floats2bfloat162_rn(o0, o1);
    op[1] = __floats2bfloat162_rn(o2, o3);
}

// ---------------- bf16 tensor-core GEMM -----------------------------------
// C[M,N] = A[M,K] @ B[K,N] (+ epilogue).
// A: bf16 row-major (loaded as k-pair uint32). B: pre-packed bf16x2 pairs [K/2][N].
// BM=BN=128, BK=32, 256 threads, 8 warps 2x4, warp tile 64x32, mma m16n8k16.
// Requires M%128==0, N%128==0, K%32==0.
#define EPI_NONE 0
#define EPI_BIAS 1
#define EPI_GELU 2
#define EPI_SIG  3
#define EPI_RES  4

#define ASTR 20    // A smem row stride (uint32): banks 20*group+tig all-distinct
#define BSTR 136   // B smem row stride (uint32): banks 8*tig+group all-distinct

template<int EPI, int OBF>
__global__ __launch_bounds__(256)
void bgemm_k(const __nv_bfloat16* __restrict__ Abf, const uint32_t* __restrict__ Bp,
             void* __restrict__ Cout, int M, int N, int K,
             const float* __restrict__ bias, const float* __restrict__ res)
{
    __shared__ uint32_t As[2][128][ASTR];   // [row][k-pair]
    __shared__ uint32_t Bs[2][16][BSTR];    // [k-pair][n]

    const uint32_t* A32 = (const uint32_t*)Abf;
    const int K2 = K >> 1;

    const int tid   = threadIdx.x;
    const int warp  = tid >> 5, lane = tid & 31;
    const int group = lane >> 2, tig = lane & 3;
    const int wm = (warp >> 2) * 64;
    const int wn = (warp & 3) * 32;
    const int m0 = blockIdx.y * 128, n0 = blockIdx.x * 128;

    // global->smem mappings (per thread: 2 uint4 for A, 2 for B)
    // A: idx -> row = idx>>2 (0..127), p4 = idx&3 (uint4 within 16-pair row)
    // B: idx -> p = (idx>>3)&15, c = (idx&7) | ((idx>>7)<<3)  (c = uint4 col 0..31)
    uint4 gA[2], gB[2];

    auto loadg = [&](int kt) {
        #pragma unroll
        for (int ld = 0; ld < 2; ld++) {
            int ia = ld * 256 + tid;
            int row = ia >> 2, p4 = ia & 3;
            gA[ld] = *(const uint4*)(A32 + (size_t)(m0 + row) * K2 + kt * 16 + p4 * 4);
            int p = (ia >> 3) & 15;
            int c = (ia & 7) | ((ia >> 7) << 3);
            gB[ld] = *(const uint4*)(Bp + (size_t)(kt * 16 + p) * N + n0 + c * 4);
        }
    };
    auto store_s = [&](int buf) {
        #pragma unroll
        for (int ld = 0; ld < 2; ld++) {
            int ia = ld * 256 + tid;
            int row = ia >> 2, p4 = ia & 3;
            *(uint4*)&As[buf][row][p4 * 4] = gA[ld];
            int p = (ia >> 3) & 15;
            int c = (ia & 7) | ((ia >> 7) << 3);
            *(uint4*)&Bs[buf][p][c * 4] = gB[ld];
        }
    };

    loadg(0);
    store_s(0);
    __syncthreads();

    float acc[4][4][4];
    #pragma unroll
    for (int mi = 0; mi < 4; mi++)
        #pragma unroll
        for (int ni = 0; ni < 4; ni++)
            #pragma unroll
            for (int r = 0; r < 4; r++) acc[mi][ni][r] = 0.f;

    const int nk = K / 32;
    for (int kt = 0; kt < nk; kt++) {
        const int buf = kt & 1;
        const bool pf = (kt + 1 < nk);
        if (pf) loadg(kt + 1);

        #pragma unroll
        for (int k16 = 0; k16 < 2; k16++) {
            const int kr0 = k16 * 8 + tig, kr1 = kr0 + 4;
            uint32_t a[4][4], b[4][2];
            #pragma unroll
            for (int mi = 0; mi < 4; mi++) {
                int mm = wm + mi * 16 + group;
                a[mi][0] = As[buf][mm][kr0];
                a[mi][1] = As[buf][mm + 8][kr0];
                a[mi][2] = As[buf][mm][kr1];
                a[mi][3] = As[buf][mm + 8][kr1];
            }
            #pragma unroll
            for (int ni = 0; ni < 4; ni++) {
                int nn = wn + ni * 8 + group;
                b[ni][0] = Bs[buf][kr0][nn];
                b[ni][1] = Bs[buf][kr1][nn];
            }
            #pragma unroll
            for (int mi = 0; mi < 4; mi++)
                #pragma unroll
                for (int ni = 0; ni < 4; ni++) {
                    asm volatile(
                        "mma.sync.aligned.m16n8k16.row.col.f32.bf16.bf16.f32 "
                        "{%0,%1,%2,%3}, {%4,%5,%6,%7}, {%8,%9}, {%0,%1,%2,%3};"
                        : "+f"(acc[mi][ni][0]), "+f"(acc[mi][ni][1]),
                          "+f"(acc[mi][ni][2]), "+f"(acc[mi][ni][3])
                        : "r"(a[mi][0]), "r"(a[mi][1]), "r"(a[mi][2]), "r"(a[mi][3]),
                          "r"(b[ni][0]), "r"(b[ni][1]));
                }
        }

        if (pf) store_s(buf ^ 1);
        __syncthreads();
    }

    // epilogue
    #pragma unroll
    for (int mi = 0; mi < 4; mi++) {
        #pragma unroll
        for (int half = 0; half < 2; half++) {
            int m = m0 + wm + mi * 16 + group + half * 8;
            #pragma unroll
            for (int ni = 0; ni < 4; ni++) {
                int n = n0 + wn + ni * 8 + tig * 2;
                float v0 = acc[mi][ni][half * 2 + 0];
                float v1 = acc[mi][ni][half * 2 + 1];
                if (EPI != EPI_NONE) { v0 += bias[n]; v1 += bias[n + 1]; }
                if (EPI == EPI_GELU) {
                    v0 = 0.5f * v0 * (1.0f + erff(v0 * 0.70710678118654752f));
                    v1 = 0.5f * v1 * (1.0f + erff(v1 * 0.70710678118654752f));
                } else if (EPI == EPI_SIG) {
                    v0 = 1.0f / (1.0f + __expf(-v0));
                    v1 = 1.0f / (1.0f + __expf(-v1));
                } else if (EPI == EPI_RES) {
                    v0 += res[(size_t)m * N + n];
                    v1 += res[(size_t)m * N + n + 1];
                }
                if (OBF) {
                    __nv_bfloat162 h2 = __floats2bfloat162_rn(v0, v1);
                    *(__nv_bfloat162*)((__nv_bfloat16*)Cout + (size_t)m * N + n) = h2;
                } else {
                    *(float2*)((float*)Cout + (size_t)m * N + n) = make_float2(v0, v1);
                }
            }
        }
    }
}

// ---------------- attention: 1 block per (b,p,h), 256 threads -------------
// qkv fp32 in, out bf16 (feeds o-proj GEMM A-side)
__global__ __launch_bounds__(256)
void attn_k(const float* __restrict__ qkv, __nv_bfloat16* __restrict__ out)
{
    extern __shared__ float sm[];
    float* Ks = sm;
    float* Vs = sm + NN * DHEAD;
    int bid = blockIdx.x;
    int h  = bid & 7;
    int bp = bid >> 3;
    int tbase = bp * NN;
    int hoff = h * DHEAD;

    for (int idx = threadIdx.x; idx < NN * DHEAD; idx += 256) {
        int r = idx >> 6, c = idx & 63;
        size_t g = (size_t)(tbase + r) * (3 * DIM);
        Ks[idx] = qkv[g + DIM     + hoff + c];
        Vs[idx] = qkv[g + 2 * DIM + hoff + c];
    }
    __syncthreads();

    int t = tbase + threadIdx.x;
    float q[64];
    {
        const float4* qp = (const float4*)(qkv + (size_t)t * (3 * DIM) + hoff);
        #pragma unroll
        for (int i = 0; i < 16; i++) {
            float4 v = qp[i];
            q[4*i] = v.x; q[4*i+1] = v.y; q[4*i+2] = v.z; q[4*i+3] = v.w;
        }
    }
    const float scale = 0.125f;

    float m = -1e30f;
    for (int j = 0; j < NN; j++) {
        const float4* kp = (const float4*)(Ks + j * 64);
        float s = 0.f;
        #pragma unroll
        for (int i = 0; i < 16; i++) {
            float4 kv = kp[i];
            s += q[4*i]*kv.x + q[4*i+1]*kv.y + q[4*i+2]*kv.z + q[4*i+3]*kv.w;
        }
        m = fmaxf(m, s * scale);
    }

    float o[64];
    #pragma unroll
    for (int i = 0; i < 64; i++) o[i] = 0.f;
    float l = 0.f;
    for (int j = 0; j < NN; j++) {
        const float4* kp = (const float4*)(Ks + j * 64);
        float s = 0.f;
        #pragma unroll
        for (int i = 0; i < 16; i++) {
            float4 kv = kp[i];
            s += q[4*i]*kv.x + q[4*i+1]*kv.y + q[4*i+2]*kv.z + q[4*i+3]*kv.w;
        }
        float p = __expf(s * scale - m);
        l += p;
        const float4* vp = (const float4*)(Vs + j * 64);
        #pragma unroll
        for (int i = 0; i < 16; i++) {
            float4 vv = vp[i];
            o[4*i]   += p * vv.x;
            o[4*i+1] += p * vv.y;
            o[4*i+2] += p * vv.z;
            o[4*i+3] += p * vv.w;
        }
    }
    float inv = 1.0f / l;
    __nv_bfloat162* op = (__nv_bfloat162*)(out + (size_t)t * DIM + hoff);
    #pragma unroll
    for (int i = 0; i < 16; i++) {
        op[2*i]   = __floats2bfloat162_rn(o[4*i]   * inv, o[4*i+1] * inv);
        op[2*i+1] = __floats2bfloat162_rn(o[4*i+2] * inv, o[4*i+3] * inv);
    }
}

// ---------------- biattn pieces ----------------
__global__ void mean_k(const __nv_bfloat16* __restrict__ bx, __nv_bfloat16* __restrict__ xg)
{
    int idx = blockIdx.x * blockDim.x + threadIdx.x;
    if (idx >= BB * NN * DIM) return;
    int d = idx % DIM;
    int n = (idx / DIM) % NN;
    int b = idx / (DIM * NN);
    size_t base = ((size_t)(b * PP) * NN + n) * DIM + d;
    const size_t st = (size_t)NN * DIM;
    float s = __bfloat162float(bx[base]) + __bfloat162float(bx[base + st])
            + __bfloat162float(bx[base + 2*st]) + __bfloat162float(bx[base + 3*st]);
    xg[idx] = __float2bfloat16(0.25f * s);
}

__global__ __launch_bounds__(256)
void sattn_k(const __nv_bfloat16* __restrict__ xl, const __nv_bfloat16* __restrict__ xga,
             const float* __restrict__ ws, const float* __restrict__ bsc,
             float* __restrict__ sa)
{
    int gtid = blockIdx.x * 256 + threadIdx.x;
    int t = gtid >> 5;
    int lane = threadIdx.x & 31;
    if (t >= TT) return;
    int b = t / (PP * NN);
    int n = t % NN;
    const __nv_bfloat16* xlp = xl  + (size_t)t * RED;
    const __nv_bfloat16* xgp = xga + ((size_t)b * NN + n) * RED;
    float s = 0.f;
    for (int i = lane; i < RED; i += 32)
        s += __bfloat162float(xlp[i]) * ws[i] + __bfloat162float(xgp[i]) * ws[RED + i];
    #pragma unroll
    for (int o = 16; o; o >>= 1) s += __shfl_xor_sync(0xffffffffu, s, o);
    if (lane == 0) sa[t] = 1.0f / (1.0f + __expf(-(s + bsc[0])));
}

__global__ void fuse_k(const float* __restrict__ h, const float* __restrict__ ca,
                       const float* __restrict__ sa, float* __restrict__ x)
{
    int idx = blockIdx.x * blockDim.x + threadIdx.x;
    if (idx >= TT * DIM) return;
    int t = idx / DIM;
    int d = idx % DIM;
    int b = t / (PP * NN);
    int n = t % NN;
    x[idx] += h[idx] * ca[((size_t)b * NN + n) * DIM + d] * sa[t];
}

// ---------------- host driver ----------------
extern "C" void kernel_launch(void* const* d_in, const int* in_sizes, int n_in,
                              void* d_out, int out_size)
{
    const float* x_in  = (const float*)d_in[0];
    const float* ln1_g = (const float*)d_in[1];
    const float* ln1_b = (const float*)d_in[2];
    const float* w_qkv = (const float*)d_in[3];
    const float* w_o   = (const float*)d_in[4];
    const float* b_o   = (const float*)d_in[5];
    const float* ln2_g = (const float*)d_in[6];
    const float* ln2_b = (const float*)d_in[7];
    const float* w1    = (const float*)d_in[8];
    const float* b1    = (const float*)d_in[9];
    const float* w2    = (const float*)d_in[10];
    const float* b2    = (const float*)d_in[11];
    const float* bn_g  = (const float*)d_in[12];
    const float* bn_b  = (const float*)d_in[13];
    const float* wg    = (const float*)d_in[14];
    const float* bg    = (const float*)d_in[15];
    const float* wl    = (const float*)d_in[16];
    const float* bl    = (const float*)d_in[17];
    const float* wc    = (const float*)d_in[18];
    const float* bc    = (const float*)d_in[19];
    const float* ws    = (const float*)d_in[20];
    const float* bs    = (const float*)d_in[21];

    float* base = nullptr;
    cudaGetSymbolAddress((void**)&base, g_scratch);
    float*          X   = base + OFF_X;
    __nv_bfloat16*  Y   = (__nv_bfloat16*)(base + OFF_Y);
    float*          QKV = base + OFF_QKV;
    __nv_bfloat16*  ATT = (__nv_bfloat16*)(base + OFF_ATT);
    __nv_bfloat16*  H1  = (__nv_bfloat16*)(base + OFF_H1);
    float*          H   = base + OFF_H;
    __nv_bfloat16*  BX  = (__nv_bfloat16*)(base + OFF_BX);
    __nv_bfloat16*  XG  = (__nv_bfloat16*)(base + OFF_XG);
    __nv_bfloat16*  XGA = (__nv_bfloat16*)(base + OFF_XGA);
    __nv_bfloat16*  XL  = (__nv_bfloat16*)(base + OFF_XL);
    float*          CA  = base + OFF_CA;
    float*          SA  = base + OFF_SA;
    uint32_t*       WP  = (uint32_t*)(base + OFF_WP);

    const int ATTN_SMEM = 2 * NN * DHEAD * sizeof(float);   // 128 KB
    cudaFuncSetAttribute((const void*)attn_k,
                         cudaFuncAttributeMaxDynamicSharedMemorySize, ATTN_SMEM);

    const int EW = 256;

    // pack all weights to bf16x2 pair layout (once per launch, ~20us)
    {
        int t;
        t = 4*256*1536; packw_k<<<(t+EW-1)/EW, EW>>>(w_qkv, WP+WP_QKV,  512, 1536, t);
        t = 4*256*512;  packw_k<<<(t+EW-1)/EW, EW>>>(w_o,   WP+WP_O,    512,  512, t);
        t = 4*256*2048; packw_k<<<(t+EW-1)/EW, EW>>>(w1,    WP+WP_W1,   512, 2048, t);
        t = 4*1024*512; packw_k<<<(t+EW-1)/EW, EW>>>(w2,    WP+WP_W2,  2048,  512, t);
        t = 4*256*128;  packw_k<<<(t+EW-1)/EW, EW>>>(wg,    WP+WP_WG,   512,  128, t);
        t = 4*256*128;  packw_k<<<(t+EW-1)/EW, EW>>>(wl,    WP+WP_WL,   512,  128, t);
        t = 4*64*512;   packw_k<<<(t+EW-1)/EW, EW>>>(wc,    WP+WP_WC,   128,  512, t);
    }

    copy_k<<<(TT*DIM + EW - 1) / EW, EW>>>(x_in, X, TT * DIM);

    for (int l = 0; l < DEPTH; l++) {
        // ---- attention half ----
        ln_k<<<TT, 128>>>(X, Y, ln1_g + l*DIM, ln1_b + l*DIM);
        bgemm_k<EPI_NONE,0><<<dim3(3*DIM/128, TT/128), 256>>>(
            Y, WP + WP_QKV + (size_t)l*256*1536, QKV, TT, 3*DIM, DIM, nullptr, nullptr);
        attn_k<<<BB*PP*HEADS, 256, ATTN_SMEM>>>(QKV, ATT);
        bgemm_k<EPI_RES,0><<<dim3(DIM/128, TT/128), 256>>>(
            ATT, WP + WP_O + (size_t)l*256*512, X, TT, DIM, DIM, b_o + l*DIM, X);

        // ---- mlp half ----
        ln_k<<<TT, 128>>>(X, Y, ln2_g + l*DIM, ln2_b + l*DIM);
        bgemm_k<EPI_GELU,1><<<dim3(MLPD/128, TT/128), 256>>>(
            Y, WP + WP_W1 + (size_t)l*256*2048, H1, TT, MLPD, DIM, b1 + l*MLPD, nullptr);
        bgemm_k<EPI_BIAS,0><<<dim3(DIM/128, TT/128), 256>>>(
            H1, WP + WP_W2 + (size_t)l*1024*512, H, TT, DIM, MLPD, b2 + l*DIM, nullptr);

        // ---- biattn ----
        ln_k<<<TT, 128>>>(H, BX, bn_g + l*DIM, bn_b + l*DIM);
        mean_k<<<(BB*NN*DIM + EW - 1) / EW, EW>>>(BX, XG);
        bgemm_k<EPI_GELU,1><<<dim3(RED/128, BB*NN/128), 256>>>(
            XG, WP + WP_WG + (size_t)l*256*128, XGA, BB*NN, RED, DIM, bg + l*RED, nullptr);
        bgemm_k<EPI_GELU,1><<<dim3(RED/128, TT/128), 256>>>(
            BX, WP + WP_WL + (size_t)l*256*128, XL, TT, RED, DIM, bl + l*RED, nullptr);
        bgemm_k<EPI_SIG,0><<<dim3(DIM/128, BB*NN/128), 256>>>(
            XGA, WP + WP_WC + (size_t)l*64*512, CA, BB*NN, DIM, RED, bc + l*DIM, nullptr);
        sattn_k<<<(TT*32 + 255) / 256, 256>>>(XL, XGA, ws + l*2*RED, bs + l, SA);
        fuse_k<<<(TT*DIM + EW - 1) / EW, EW>>>(H, CA, SA, X);
    }

    copy_k<<<(TT*DIM + EW - 1) / EW, EW>>>(X, (float*)d_out, TT * DIM);
}